// round 12
// baseline (speedup 1.0000x reference)
#include <cuda_runtime.h>
#include <cstdint>
#include <math.h>

#define H 2048
#define L 350

// -------- persistent scratch (no allocs allowed) --------
__device__ float g_lp[2][L];               // attn logit partials (x-half, h-half)
// layout: [0,2048) x copy | [2048,4096) ctx (atomic) | [4096,6144) gsum (atomic)
// | [6144,12288) gi (atomic) | [12288,18432) gh (atomic) | [18432,20480) g=relu vec
#define SC_VEC   0
#define SC_CTX   2048
#define SC_GSUM  4096
#define SC_GI    6144
#define SC_GH    12288
#define SC_G     18432
#define SC_TOTAL 20480
__device__ __align__(16) float g_scr[SC_TOTAL];
__device__ int g_kd_done;                  // kD completion counter (self-resetting)
__device__ int g_ke_done;                  // kE completion counter (self-resetting)

__device__ __forceinline__ float warp_sum(float v) {
    #pragma unroll
    for (int o = 16; o > 0; o >>= 1) v += __shfl_xor_sync(0xffffffffu, v, o);
    return v;
}
__device__ __forceinline__ float dot4(float4 a, float4 b) {
    return a.x*b.x + a.y*b.y + a.z*b.z + a.w*b.w;
}

// R5-proven unit: ONE front-batched burst of 8 LDG.128 (32 regs, ptxas keeps
// it resident) + 8 vector loads from global (L1/L2-hot). 256 float4 segment.
__device__ __forceinline__ float seg_dot8(
    const float4* __restrict__ W, const float4* __restrict__ V, int lane)
{
    float4 w[8];
    #pragma unroll
    for (int u = 0; u < 8; u++) w[u] = __ldcs(&W[lane + 32*u]);
    float s = 0.f;
    #pragma unroll
    for (int u = 0; u < 8; u++) s += dot4(w[u], V[lane + 32*u]);
    return s;
}

// ============================================================
// kA: warps [0,700)   attn logit partials (warp per (row,half), 2 bursts)
//     warps [700,828) zero atomic scratch [2048,18432)
//     warps [828,844) copy x -> g_scr[SC_VEC]
// ============================================================
#define KA_BLOCKS 106    // 848 warps
__global__ __launch_bounds__(256) void kA(
    const float* __restrict__ x, const float* __restrict__ h,
    const float* __restrict__ attn_W)
{
    int warp = (blockIdx.x * blockDim.x + threadIdx.x) >> 5;
    int lane = threadIdx.x & 31;

    if (warp < 700) {
        int row = warp >> 1, half = warp & 1;
        const float4* W = (const float4*)(attn_W + (size_t)row * 2 * H) + half * 512;
        const float4* v = (const float4*)(half ? h : x);
        float s = seg_dot8(W, v, lane) + seg_dot8(W + 256, v + 256, lane);
        s = warp_sum(s);
        if (lane == 0) g_lp[half][row] = s;
    } else if (warp < 828) {
        int z = warp - 700;                       // zero [2048,18432): 128 warps
        *(float4*)(g_scr + 2048 + z * 128 + lane * 4) = make_float4(0.f,0.f,0.f,0.f);
    } else if (warp < 844) {
        int z = warp - 828;                       // copy x -> [0,2048)
        int i = z * 32 + lane;
        ((float4*)(g_scr + SC_VEC))[i] = ((const float4*)x)[i];
    }
}

// ============================================================
// kBC: blocks [0,112)   redundant softmax (L2-hot) + ctx partial (atomic)
//      blocks [112,800) w_hh rows 0..2751, warp per (row,half), atomic gh
// ============================================================
#define KBC_BLOCKS 800
__global__ __launch_bounds__(256) void kBC(
    const float* __restrict__ h, const float* __restrict__ attn_b,
    const float* __restrict__ enc, const float* __restrict__ w_hh,
    float* __restrict__ out)
{
    int tid = threadIdx.x;

    if (blockIdx.x < 112) {
        __shared__ float sw[L];
        __shared__ float red[256];
        float m = -INFINITY;
        for (int i = tid; i < L; i += 256) {
            float v = g_lp[0][i] + g_lp[1][i] + attn_b[i];
            sw[i] = v; m = fmaxf(m, v);
        }
        red[tid] = m; __syncthreads();
        #pragma unroll
        for (int s = 128; s > 0; s >>= 1) { if (tid < s) red[tid] = fmaxf(red[tid], red[tid+s]); __syncthreads(); }
        float mx = red[0]; __syncthreads();

        float sum = 0.f;
        for (int i = tid; i < L; i += 256) { float e = __expf(sw[i] - mx); sw[i] = e; sum += e; }
        red[tid] = sum; __syncthreads();
        #pragma unroll
        for (int s = 128; s > 0; s >>= 1) { if (tid < s) red[tid] += red[tid+s]; __syncthreads(); }
        float inv = 1.f / red[0]; __syncthreads();
        for (int i = tid; i < L; i += 256) sw[i] *= inv;
        __syncthreads();

        if (blockIdx.x == 0)
            for (int i = tid; i < L; i += 256) out[2*H + i] = sw[i];

        int bx = blockIdx.x & 7, by = blockIdx.x >> 3;
        int j  = bx * 256 + tid;
        int r0 = by * 25;
        const float* e = enc + (size_t)r0 * H + j;
        float acc = 0.f;
        #pragma unroll
        for (int i = 0; i < 25; ++i)
            acc += sw[r0 + i] * e[(size_t)i * H];
        atomicAdd(&g_scr[SC_CTX + j], acc);
    } else {
        int lane = tid & 31;
        int gw = (blockIdx.x - 112) * 8 + (tid >> 5);  // 0..5503
        int row = gw >> 1, half = gw & 1;              // rows 0..2751
        const float4* W = (const float4*)w_hh + (size_t)row * 512 + half * 256;
        const float4* v = (const float4*)h + half * 256;
        float s = seg_dot8(W, v, lane);
        s = warp_sum(s);
        if (lane == 0) atomicAdd(&g_scr[SC_GH + row], s);
    }
}

// ============================================================
// kD: blocks [0,1024)    comb_W @ [x;ctx], warp per (row,quarter), atomic gsum
//     blocks [1024,1872) w_hh rows 2752..6143, warp per (row,half), atomic gh
// Last block materializes g = relu(gsum + comb_b) -> SC_G.
// ============================================================
#define KD_BLOCKS 1872
__global__ __launch_bounds__(256) void kD(
    const float* __restrict__ h,
    const float* __restrict__ comb_W, const float* __restrict__ w_hh,
    const float* __restrict__ comb_b)
{
    __shared__ int is_last;
    int tid  = threadIdx.x;
    int lane = tid & 31;
    int gw   = blockIdx.x * 8 + (tid >> 5);

    if (blockIdx.x < 1024) {
        int row = gw >> 2, q = gw & 3;                 // 2048 rows x 4 quarters
        const float4* W = (const float4*)comb_W + (size_t)row * 1024 + q * 256;
        const float4* v = (const float4*)(g_scr + SC_VEC) + q * 256;
        float s = seg_dot8(W, v, lane);
        s = warp_sum(s);
        if (lane == 0) atomicAdd(&g_scr[SC_GSUM + row], s);
    } else {
        int t = gw - 8192;                             // 0..6783
        int row = 2752 + (t >> 1), half = t & 1;       // rows 2752..6143
        const float4* W = (const float4*)w_hh + (size_t)row * 512 + half * 256;
        const float4* v = (const float4*)h + half * 256;
        float s = seg_dot8(W, v, lane);
        s = warp_sum(s);
        if (lane == 0) atomicAdd(&g_scr[SC_GH + row], s);
    }

    // last-block epilogue: g = relu(gsum + comb_b)
    __syncthreads();
    if (tid == 0) {
        __threadfence();
        int old = atomicAdd(&g_kd_done, 1);
        is_last = (old == KD_BLOCKS - 1);
    }
    __syncthreads();
    if (is_last) {
        if (tid == 0) g_kd_done = 0;
        for (int j = tid; j < H; j += 256)
            g_scr[SC_G + j] = fmaxf(g_scr[SC_GSUM + j] + comb_b[j], 0.f);
    }
}

// ============================================================
// kE: gi = w_ih @ g, warp per (row,half), atomic gi.  2 streams only.
// Last block runs the GRU gate epilogue.
// ============================================================
#define KE_BLOCKS 1536
__global__ __launch_bounds__(256) void kE(
    const float* __restrict__ w_ih,
    const float* __restrict__ h, const float* __restrict__ b_ih,
    const float* __restrict__ b_hh, float* __restrict__ out)
{
    __shared__ int is_last;
    int tid  = threadIdx.x;
    int lane = tid & 31;
    int gw   = blockIdx.x * 8 + (tid >> 5);           // 0..12287
    int row  = gw >> 1, half = gw & 1;                // 6144 rows

    const float4* W = (const float4*)w_ih + (size_t)row * 512 + half * 256;
    const float4* v = (const float4*)(g_scr + SC_G) + half * 256;
    float s = seg_dot8(W, v, lane);
    s = warp_sum(s);
    if (lane == 0) atomicAdd(&g_scr[SC_GI + row], s);

    // last-block epilogue
    __syncthreads();
    if (tid == 0) {
        __threadfence();
        int old = atomicAdd(&g_ke_done, 1);
        is_last = (old == KE_BLOCKS - 1);
    }
    __syncthreads();
    if (is_last) {
        if (tid == 0) g_ke_done = 0;
        __threadfence();
        for (int j = tid; j < H; j += 256) {
            float hr = g_scr[SC_GH + j]       + b_hh[j];
            float hz = g_scr[SC_GH + j + H]   + b_hh[j + H];
            float hn = g_scr[SC_GH + j + 2*H] + b_hh[j + 2*H];
            float ir = g_scr[SC_GI + j]       + b_ih[j]       + hr;
            float iz = g_scr[SC_GI + j + H]   + b_ih[j + H]   + hz;
            float r  = 1.f / (1.f + __expf(-ir));
            float z  = 1.f / (1.f + __expf(-iz));
            float n  = tanhf(g_scr[SC_GI + j + 2*H] + b_ih[j + 2*H] + r * hn);
            float hv = (1.f - z) * n + z * h[j];
            out[j]     = hv;
            out[H + j] = hv;
        }
    }
}

// ============================================================
extern "C" void kernel_launch(void* const* d_in, const int* in_sizes, int n_in,
                              void* d_out, int out_size)
{
    const float* x      = (const float*)d_in[0];
    const float* h      = (const float*)d_in[1];
    const float* enc    = (const float*)d_in[2];
    const float* attn_W = (const float*)d_in[3];
    const float* attn_b = (const float*)d_in[4];
    const float* comb_W = (const float*)d_in[5];
    const float* comb_b = (const float*)d_in[6];
    const float* w_ih   = (const float*)d_in[7];
    const float* w_hh   = (const float*)d_in[8];
    const float* b_ih   = (const float*)d_in[9];
    const float* b_hh   = (const float*)d_in[10];
    float* out = (float*)d_out;

    kA<<<KA_BLOCKS, 256>>>(x, h, attn_W);
    kBC<<<KBC_BLOCKS, 256>>>(h, attn_b, enc, w_hh, out);
    kD<<<KD_BLOCKS, 256>>>(h, comb_W, w_hh, comb_b);
    kE<<<KE_BLOCKS, 256>>>(w_ih, h, b_ih, b_hh, out);
}

// round 13
// speedup vs baseline: 1.1354x; 1.1354x over previous
#include <cuda_runtime.h>
#include <cstdint>
#include <math.h>

#define H 2048
#define L 350

// -------- persistent scratch (no allocs allowed) --------
__device__ float g_lp[2][L];               // attn logit partials (x-half, h-half)
// layout: [0,2048) x copy | [2048,4096) ctx (atomic, zeroed) |
// [4096,6144) gsum (atomic, zeroed) | [6144,12288) gi (direct) |
// [12288,18432) gh (direct) | [18432,20480) g = relu vec
#define SC_VEC   0
#define SC_CTX   2048
#define SC_GSUM  4096
#define SC_GI    6144
#define SC_GH    12288
#define SC_G     18432
#define SC_TOTAL 20480
__device__ __align__(16) float g_scr[SC_TOTAL];

__device__ __forceinline__ float warp_sum(float v) {
    #pragma unroll
    for (int o = 16; o > 0; o >>= 1) v += __shfl_xor_sync(0xffffffffu, v, o);
    return v;
}
__device__ __forceinline__ float dot4(float4 a, float4 b) {
    return a.x*b.x + a.y*b.y + a.z*b.z + a.w*b.w;
}

// R5-proven unit: ONE front-batched burst of 8 LDG.128 (32 regs resident),
// then 8 dots against an L1/L2-hot global vector. 256 float4 segment.
__device__ __forceinline__ float seg_dot8(
    const float4* __restrict__ W, const float4* __restrict__ V, int lane)
{
    float4 w[8];
    #pragma unroll
    for (int u = 0; u < 8; u++) w[u] = __ldcs(&W[lane + 32*u]);
    float s = 0.f;
    #pragma unroll
    for (int u = 0; u < 8; u++) s += dot4(w[u], V[lane + 32*u]);
    return s;
}

// Full 2048-col row (512 f4): two bursts, direct result.
__device__ __forceinline__ float row_dot(
    const float4* __restrict__ W, const float4* __restrict__ V, int lane)
{
    return seg_dot8(W, V, lane) + seg_dot8(W + 256, V + 256, lane);
}

// ============================================================
// kA: warps [0,700)     attn logit partials (warp per (row,half))
//     warps [700,732)   zero ctx+gsum [2048,6144)
//     warps [732,748)   copy x -> g_scr[SC_VEC]
//     warps [748,1772)  w_hh rows 0..1023 (warp per row, direct store)
// ============================================================
#define KA_WARPS 1772
#define KA_BLOCKS ((KA_WARPS + 7) / 8)
__global__ __launch_bounds__(256) void kA(
    const float* __restrict__ x, const float* __restrict__ h,
    const float* __restrict__ attn_W, const float* __restrict__ w_hh)
{
    int warp = (blockIdx.x * blockDim.x + threadIdx.x) >> 5;
    int lane = threadIdx.x & 31;
    const float4* h4 = (const float4*)h;

    if (warp < 700) {
        int row = warp >> 1, half = warp & 1;
        const float4* W = (const float4*)(attn_W + (size_t)row * 2 * H) + half * 512;
        const float4* v = (const float4*)(half ? h : x);
        float s = row_dot(W, v, lane);
        s = warp_sum(s);
        if (lane == 0) g_lp[half][row] = s;
    } else if (warp < 732) {
        int z = warp - 700;                       // zero [2048,6144): 32 warps
        *(float4*)(g_scr + 2048 + z * 128 + lane * 4) = make_float4(0.f,0.f,0.f,0.f);
    } else if (warp < 748) {
        int z = warp - 732;                       // copy x -> [0,2048)
        int i = z * 32 + lane;
        ((float4*)(g_scr + SC_VEC))[i] = ((const float4*)x)[i];
    } else if (warp < KA_WARPS) {
        int row = warp - 748;                     // w_hh rows 0..1023
        const float4* W = (const float4*)w_hh + (size_t)row * 512;
        float s = row_dot(W, h4, lane);
        s = warp_sum(s);
        if (lane == 0) g_scr[SC_GH + row] = s;
    }
}

// ============================================================
// kBC: blocks [0,112)   redundant softmax (L2-hot) + ctx partial (atomic)
//      blocks [112,368) w_hh rows 1024..3071 (warp per row, direct)
// ============================================================
#define KBC_BLOCKS 368
__global__ __launch_bounds__(256) void kBC(
    const float* __restrict__ h, const float* __restrict__ attn_b,
    const float* __restrict__ enc, const float* __restrict__ w_hh,
    float* __restrict__ out)
{
    int tid = threadIdx.x;

    if (blockIdx.x < 112) {
        __shared__ float sw[L];
        __shared__ float red[256];
        float m = -INFINITY;
        for (int i = tid; i < L; i += 256) {
            float v = g_lp[0][i] + g_lp[1][i] + attn_b[i];
            sw[i] = v; m = fmaxf(m, v);
        }
        red[tid] = m; __syncthreads();
        #pragma unroll
        for (int s = 128; s > 0; s >>= 1) { if (tid < s) red[tid] = fmaxf(red[tid], red[tid+s]); __syncthreads(); }
        float mx = red[0]; __syncthreads();

        float sum = 0.f;
        for (int i = tid; i < L; i += 256) { float e = __expf(sw[i] - mx); sw[i] = e; sum += e; }
        red[tid] = sum; __syncthreads();
        #pragma unroll
        for (int s = 128; s > 0; s >>= 1) { if (tid < s) red[tid] += red[tid+s]; __syncthreads(); }
        float inv = 1.f / red[0]; __syncthreads();
        for (int i = tid; i < L; i += 256) sw[i] *= inv;
        __syncthreads();

        if (blockIdx.x == 0)
            for (int i = tid; i < L; i += 256) out[2*H + i] = sw[i];

        int bx = blockIdx.x & 7, by = blockIdx.x >> 3;
        int j  = bx * 256 + tid;
        int r0 = by * 25;
        const float* e = enc + (size_t)r0 * H + j;
        float acc = 0.f;
        #pragma unroll
        for (int i = 0; i < 25; ++i)
            acc += sw[r0 + i] * e[(size_t)i * H];
        atomicAdd(&g_scr[SC_CTX + j], acc);
    } else {
        int lane = tid & 31;
        int row = 1024 + (blockIdx.x - 112) * 8 + (tid >> 5);  // 1024..3071
        const float4* W = (const float4*)w_hh + (size_t)row * 512;
        float s = row_dot(W, (const float4*)h, lane);
        s = warp_sum(s);
        if (lane == 0) g_scr[SC_GH + row] = s;
    }
}

// ============================================================
// kD: blocks [0,1024)     comb_W @ [x;ctx], warp per (row,quarter), atomic
//     blocks [1024,1408)  w_hh rows 3072..6143 (warp per row, direct)
// No block tails.
// ============================================================
#define KD_BLOCKS 1408
__global__ __launch_bounds__(256) void kD(
    const float* __restrict__ h,
    const float* __restrict__ comb_W, const float* __restrict__ w_hh)
{
    int tid  = threadIdx.x;
    int lane = tid & 31;

    if (blockIdx.x < 1024) {
        int gw = blockIdx.x * 8 + (tid >> 5);
        int row = gw >> 2, q = gw & 3;                 // 2048 rows x 4 quarters
        const float4* W = (const float4*)comb_W + (size_t)row * 1024 + q * 256;
        const float4* v = (const float4*)(g_scr + SC_VEC) + q * 256;
        float s = seg_dot8(W, v, lane);
        s = warp_sum(s);
        if (lane == 0) atomicAdd(&g_scr[SC_GSUM + row], s);
    } else {
        int row = 3072 + (blockIdx.x - 1024) * 8 + (tid >> 5);  // 3072..6143
        const float4* W = (const float4*)w_hh + (size_t)row * 512;
        float s = row_dot(W, (const float4*)h, lane);
        s = warp_sum(s);
        if (lane == 0) g_scr[SC_GH + row] = s;
    }
}

// ============================================================
// kG: tiny — g = relu(gsum + comb_b)
// ============================================================
__global__ __launch_bounds__(256) void kG(const float* __restrict__ comb_b)
{
    int j = blockIdx.x * 256 + threadIdx.x;
    g_scr[SC_G + j] = fmaxf(g_scr[SC_GSUM + j] + comb_b[j], 0.f);
}

// ============================================================
// kE: gi = w_ih @ g, warp per FULL row, direct store, no tails.
// ============================================================
#define KE_BLOCKS 768
__global__ __launch_bounds__(256) void kE(const float* __restrict__ w_ih)
{
    int lane = threadIdx.x & 31;
    int row  = blockIdx.x * 8 + (threadIdx.x >> 5);   // 6144 rows
    const float4* W = (const float4*)w_ih + (size_t)row * 512;
    const float4* v = (const float4*)(g_scr + SC_G);
    float s = row_dot(W, v, lane);
    s = warp_sum(s);
    if (lane == 0) g_scr[SC_GI + row] = s;
}

// ============================================================
// kF: tiny — GRU gates + outputs
// ============================================================
__global__ __launch_bounds__(256) void kF(
    const float* __restrict__ h, const float* __restrict__ b_ih,
    const float* __restrict__ b_hh, float* __restrict__ out)
{
    int j = blockIdx.x * 256 + threadIdx.x;
    float hr = g_scr[SC_GH + j]       + b_hh[j];
    float hz = g_scr[SC_GH + j + H]   + b_hh[j + H];
    float hn = g_scr[SC_GH + j + 2*H] + b_hh[j + 2*H];
    float ir = g_scr[SC_GI + j]       + b_ih[j]       + hr;
    float iz = g_scr[SC_GI + j + H]   + b_ih[j + H]   + hz;
    float r  = 1.f / (1.f + __expf(-ir));
    float z  = 1.f / (1.f + __expf(-iz));
    float n  = tanhf(g_scr[SC_GI + j + 2*H] + b_ih[j + 2*H] + r * hn);
    float hv = (1.f - z) * n + z * h[j];
    out[j]     = hv;
    out[H + j] = hv;
}

// ============================================================
extern "C" void kernel_launch(void* const* d_in, const int* in_sizes, int n_in,
                              void* d_out, int out_size)
{
    const float* x      = (const float*)d_in[0];
    const float* h      = (const float*)d_in[1];
    const float* enc    = (const float*)d_in[2];
    const float* attn_W = (const float*)d_in[3];
    const float* attn_b = (const float*)d_in[4];
    const float* comb_W = (const float*)d_in[5];
    const float* comb_b = (const float*)d_in[6];
    const float* w_ih   = (const float*)d_in[7];
    const float* w_hh   = (const float*)d_in[8];
    const float* b_ih   = (const float*)d_in[9];
    const float* b_hh   = (const float*)d_in[10];
    float* out = (float*)d_out;

    kA<<<KA_BLOCKS, 256>>>(x, h, attn_W, w_hh);
    kBC<<<KBC_BLOCKS, 256>>>(h, attn_b, enc, w_hh, out);
    kD<<<KD_BLOCKS, 256>>>(h, comb_W, w_hh);
    kG<<<H / 256, 256>>>(comb_b);
    kE<<<KE_BLOCKS, 256>>>(w_ih);
    kF<<<H / 256, 256>>>(h, b_ih, b_hh, out);
}

// round 15
// speedup vs baseline: 1.2117x; 1.0672x over previous
#include <cuda_runtime.h>
#include <cstdint>
#include <math.h>

#define H 2048
#define L 350

// -------- persistent scratch (no allocs allowed) --------
__device__ float g_lp[2][L];               // attn logit partials (x-half, h-half)
// layout: [0,2048) x copy | [2048,4096) ctx (atomic, zeroed) |
// [4096,6144) gsum (atomic, zeroed) | [12288,18432) gh (direct)
#define SC_VEC   0
#define SC_CTX   2048
#define SC_GSUM  4096
#define SC_GH    12288
#define SC_TOTAL 18432
__device__ __align__(16) float g_scr[SC_TOTAL];

__device__ __forceinline__ float warp_sum(float v) {
    #pragma unroll
    for (int o = 16; o > 0; o >>= 1) v += __shfl_xor_sync(0xffffffffu, v, o);
    return v;
}
__device__ __forceinline__ float dot4(float4 a, float4 b) {
    return a.x*b.x + a.y*b.y + a.z*b.z + a.w*b.w;
}

// Proven unit: ONE front-batched burst of 8 LDG.128 (32 regs resident),
// then 8 dots against a hot vector (global-L2 or smem). 256 float4 segment.
__device__ __forceinline__ float seg_dot8(
    const float4* __restrict__ W, const float4* V, int lane)
{
    float4 w[8];
    #pragma unroll
    for (int u = 0; u < 8; u++) w[u] = __ldcs(&W[lane + 32*u]);
    float s = 0.f;
    #pragma unroll
    for (int u = 0; u < 8; u++) s += dot4(w[u], V[lane + 32*u]);
    return s;
}

// Full 2048-col row (512 f4): two sequential bursts.
__device__ __forceinline__ float row_dot(
    const float4* __restrict__ W, const float4* V, int lane)
{
    return seg_dot8(W, V, lane) + seg_dot8(W + 256, V + 256, lane);
}

// ============================================================
// kA: warps [0,700)     attn logit partials (warp per (row,half))
//     warps [700,732)   zero ctx+gsum [2048,6144)
//     warps [732,748)   copy x -> g_scr[SC_VEC]
//     warps [748,1772)  w_hh rows 0..1023 (warp per row, direct store)
// ============================================================
#define KA_WARPS 1772
#define KA_BLOCKS ((KA_WARPS + 7) / 8)
__global__ __launch_bounds__(256) void kA(
    const float* __restrict__ x, const float* __restrict__ h,
    const float* __restrict__ attn_W, const float* __restrict__ w_hh)
{
    int warp = (blockIdx.x * blockDim.x + threadIdx.x) >> 5;
    int lane = threadIdx.x & 31;
    const float4* h4 = (const float4*)h;

    if (warp < 700) {
        int row = warp >> 1, half = warp & 1;
        const float4* W = (const float4*)(attn_W + (size_t)row * 2 * H) + half * 512;
        const float4* v = (const float4*)(half ? h : x);
        float s = row_dot(W, v, lane);
        s = warp_sum(s);
        if (lane == 0) g_lp[half][row] = s;
    } else if (warp < 732) {
        int z = warp - 700;                       // zero [2048,6144): 32 warps
        *(float4*)(g_scr + 2048 + z * 128 + lane * 4) = make_float4(0.f,0.f,0.f,0.f);
    } else if (warp < 748) {
        int z = warp - 732;                       // copy x -> [0,2048)
        int i = z * 32 + lane;
        ((float4*)(g_scr + SC_VEC))[i] = ((const float4*)x)[i];
    } else if (warp < KA_WARPS) {
        int row = warp - 748;                     // w_hh rows 0..1023
        const float4* W = (const float4*)w_hh + (size_t)row * 512;
        float s = row_dot(W, h4, lane);
        s = warp_sum(s);
        if (lane == 0) g_scr[SC_GH + row] = s;
    }
}

// ============================================================
// kBC: blocks [0,112)   redundant softmax (L2-hot) + ctx partial (atomic)
//      blocks [112,368) w_hh rows 1024..3071 (warp per row, direct)
// ============================================================
#define KBC_BLOCKS 368
__global__ __launch_bounds__(256) void kBC(
    const float* __restrict__ h, const float* __restrict__ attn_b,
    const float* __restrict__ enc, const float* __restrict__ w_hh,
    float* __restrict__ out)
{
    int tid = threadIdx.x;

    if (blockIdx.x < 112) {
        __shared__ float sw[L];
        __shared__ float red[256];
        float m = -INFINITY;
        for (int i = tid; i < L; i += 256) {
            float v = g_lp[0][i] + g_lp[1][i] + attn_b[i];
            sw[i] = v; m = fmaxf(m, v);
        }
        red[tid] = m; __syncthreads();
        #pragma unroll
        for (int s = 128; s > 0; s >>= 1) { if (tid < s) red[tid] = fmaxf(red[tid], red[tid+s]); __syncthreads(); }
        float mx = red[0]; __syncthreads();

        float sum = 0.f;
        for (int i = tid; i < L; i += 256) { float e = __expf(sw[i] - mx); sw[i] = e; sum += e; }
        red[tid] = sum; __syncthreads();
        #pragma unroll
        for (int s = 128; s > 0; s >>= 1) { if (tid < s) red[tid] += red[tid+s]; __syncthreads(); }
        float inv = 1.f / red[0]; __syncthreads();
        for (int i = tid; i < L; i += 256) sw[i] *= inv;
        __syncthreads();

        if (blockIdx.x == 0)
            for (int i = tid; i < L; i += 256) out[2*H + i] = sw[i];

        int bx = blockIdx.x & 7, by = blockIdx.x >> 3;
        int j  = bx * 256 + tid;
        int r0 = by * 25;
        const float* e = enc + (size_t)r0 * H + j;
        float acc = 0.f;
        #pragma unroll
        for (int i = 0; i < 25; ++i)
            acc += sw[r0 + i] * e[(size_t)i * H];
        atomicAdd(&g_scr[SC_CTX + j], acc);
    } else {
        int lane = tid & 31;
        int row = 1024 + (blockIdx.x - 112) * 8 + (tid >> 5);  // 1024..3071
        const float4* W = (const float4*)w_hh + (size_t)row * 512;
        float s = row_dot(W, (const float4*)h, lane);
        s = warp_sum(s);
        if (lane == 0) g_scr[SC_GH + row] = s;
    }
}

// ============================================================
// kD: blocks [0,1024)     comb_W @ [x;ctx], warp per (row,quarter), atomic
//     blocks [1024,1408)  w_hh rows 3072..6143 (warp per row, direct)
// No block tails.
// ============================================================
#define KD_BLOCKS 1408
__global__ __launch_bounds__(256) void kD(
    const float* __restrict__ h,
    const float* __restrict__ comb_W, const float* __restrict__ w_hh)
{
    int tid  = threadIdx.x;
    int lane = tid & 31;

    if (blockIdx.x < 1024) {
        int gw = blockIdx.x * 8 + (tid >> 5);
        int row = gw >> 2, q = gw & 3;                 // 2048 rows x 4 quarters
        const float4* W = (const float4*)comb_W + (size_t)row * 1024 + q * 256;
        const float4* v = (const float4*)(g_scr + SC_VEC) + q * 256;
        float s = seg_dot8(W, v, lane);
        s = warp_sum(s);
        if (lane == 0) atomicAdd(&g_scr[SC_GSUM + row], s);
    } else {
        int row = 3072 + (blockIdx.x - 1024) * 8 + (tid >> 5);  // 3072..6143
        const float4* W = (const float4*)w_hh + (size_t)row * 512;
        float s = row_dot(W, (const float4*)h, lane);
        s = warp_sum(s);
        if (lane == 0) g_scr[SC_GH + row] = s;
    }
}

// ============================================================
// kE: FULLY FUSED final stage. 256 blocks x 8 warps.
//   stage: g = relu(gsum + comb_b) -> smem (folds old kG)
//   warp w (col j): 3 full row-dots over w_ih rows j, j+H, j+2H (6 bursts),
//   then lane 0 does complete GRU gate math + writes out (folds old kF).
// No gi scratch, no epilogue kernel, no block tails after the dots.
// ============================================================
#define KE_BLOCKS 256
__global__ __launch_bounds__(256) void kE(
    const float* __restrict__ w_ih, const float* __restrict__ comb_b,
    const float* __restrict__ h, const float* __restrict__ b_ih,
    const float* __restrict__ b_hh, float* __restrict__ out)
{
    __shared__ __align__(16) float sg[H];
    int tid  = threadIdx.x;
    int lane = tid & 31;
    int wid  = tid >> 5;

    // stage g = relu(gsum + comb_b)
    const float4* gs = (const float4*)(g_scr + SC_GSUM);
    const float4* cb = (const float4*)comb_b;
    float4* sg4 = (float4*)sg;
    #pragma unroll
    for (int i = tid; i < 512; i += 256) {
        float4 gv = gs[i], bv = cb[i];
        sg4[i] = make_float4(fmaxf(gv.x + bv.x, 0.f), fmaxf(gv.y + bv.y, 0.f),
                             fmaxf(gv.z + bv.z, 0.f), fmaxf(gv.w + bv.w, 0.f));
    }
    __syncthreads();

    int j = blockIdx.x * 8 + wid;                 // output column 0..2047
    const float4* v  = (const float4*)sg;
    const float4* Wr = (const float4*)w_ih + (size_t)j * 512;
    const float4* Wz = (const float4*)w_ih + (size_t)(j + H) * 512;
    const float4* Wn = (const float4*)w_ih + (size_t)(j + 2*H) * 512;

    float sr = row_dot(Wr, v, lane);
    float sz = row_dot(Wz, v, lane);
    float sn = row_dot(Wn, v, lane);
    sr = warp_sum(sr); sz = warp_sum(sz); sn = warp_sum(sn);

    if (lane == 0) {
        float hr = g_scr[SC_GH + j]       + b_hh[j];
        float hz = g_scr[SC_GH + j + H]   + b_hh[j + H];
        float hn = g_scr[SC_GH + j + 2*H] + b_hh[j + 2*H];
        float ir = sr + b_ih[j]       + hr;
        float iz = sz + b_ih[j + H]   + hz;
        float r  = 1.f / (1.f + __expf(-ir));
        float z  = 1.f / (1.f + __expf(-iz));
        float n  = tanhf(sn + b_ih[j + 2*H] + r * hn);
        float hv = (1.f - z) * n + z * h[j];
        out[j]     = hv;
        out[H + j] = hv;
    }
}

// ============================================================
extern "C" void kernel_launch(void* const* d_in, const int* in_sizes, int n_in,
                              void* d_out, int out_size)
{
    const float* x      = (const float*)d_in[0];
    const float* h      = (const float*)d_in[1];
    const float* enc    = (const float*)d_in[2];
    const float* attn_W = (const float*)d_in[3];
    const float* attn_b = (const float*)d_in[4];
    const float* comb_W = (const float*)d_in[5];
    const float* comb_b = (const float*)d_in[6];
    const float* w_ih   = (const float*)d_in[7];
    const float* w_hh   = (const float*)d_in[8];
    const float* b_ih   = (const float*)d_in[9];
    const float* b_hh   = (const float*)d_in[10];
    float* out = (float*)d_out;

    kA<<<KA_BLOCKS, 256>>>(x, h, attn_W, w_hh);
    kBC<<<KBC_BLOCKS, 256>>>(h, attn_b, enc, w_hh, out);
    kD<<<KD_BLOCKS, 256>>>(h, comb_W, w_hh);
    kE<<<KE_BLOCKS, 256>>>(w_ih, comb_b, h, b_ih, b_hh, out);
}

// round 16
// speedup vs baseline: 1.2744x; 1.0518x over previous
#include <cuda_runtime.h>
#include <cstdint>
#include <math.h>

#define H 2048
#define L 350

// -------- persistent scratch (no allocs allowed) --------
__device__ float g_lp[2][L];               // attn logit partials (x-half, h-half)
// layout: [0,2048) x copy | [2048,4096) ctx (atomic, zeroed) |
// [4096,6144) gsum (atomic, zeroed) | [12288,18432) gh (direct)
#define SC_VEC   0
#define SC_CTX   2048
#define SC_GSUM  4096
#define SC_GH    12288
#define SC_TOTAL 18432
__device__ __align__(16) float g_scr[SC_TOTAL];

__device__ __forceinline__ float warp_sum(float v) {
    #pragma unroll
    for (int o = 16; o > 0; o >>= 1) v += __shfl_xor_sync(0xffffffffu, v, o);
    return v;
}
__device__ __forceinline__ float dot4(float4 a, float4 b) {
    return a.x*b.x + a.y*b.y + a.z*b.z + a.w*b.w;
}

// Proven unit: ONE front-batched burst of 8 LDG.128 (32 regs resident),
// then 8 dots against a hot vector (global-L2 or smem). 256 float4 segment.
__device__ __forceinline__ float seg_dot8(
    const float4* __restrict__ W, const float4* V, int lane)
{
    float4 w[8];
    #pragma unroll
    for (int u = 0; u < 8; u++) w[u] = __ldcs(&W[lane + 32*u]);
    float s = 0.f;
    #pragma unroll
    for (int u = 0; u < 8; u++) s += dot4(w[u], V[lane + 32*u]);
    return s;
}

// Full 2048-col row (512 f4): two sequential bursts.
__device__ __forceinline__ float row_dot(
    const float4* __restrict__ W, const float4* V, int lane)
{
    return seg_dot8(W, V, lane) + seg_dot8(W + 256, V + 256, lane);
}

// ============================================================
// kA: warps [0,700)     attn logit partials (warp per (row,half))
//     warps [700,732)   zero ctx+gsum [2048,6144)
//     warps [732,748)   copy x -> g_scr[SC_VEC]
//     warps [748,1772)  w_hh rows 0..1023 (warp per row, direct store)
// ============================================================
#define KA_WARPS 1772
#define KA_BLOCKS ((KA_WARPS + 7) / 8)
__global__ __launch_bounds__(256) void kA(
    const float* __restrict__ x, const float* __restrict__ h,
    const float* __restrict__ attn_W, const float* __restrict__ w_hh)
{
    int warp = (blockIdx.x * blockDim.x + threadIdx.x) >> 5;
    int lane = threadIdx.x & 31;
    const float4* h4 = (const float4*)h;

    if (warp < 700) {
        int row = warp >> 1, half = warp & 1;
        const float4* W = (const float4*)(attn_W + (size_t)row * 2 * H) + half * 512;
        const float4* v = (const float4*)(half ? h : x);
        float s = row_dot(W, v, lane);
        s = warp_sum(s);
        if (lane == 0) g_lp[half][row] = s;
    } else if (warp < 732) {
        int z = warp - 700;                       // zero [2048,6144): 32 warps
        *(float4*)(g_scr + 2048 + z * 128 + lane * 4) = make_float4(0.f,0.f,0.f,0.f);
    } else if (warp < 748) {
        int z = warp - 732;                       // copy x -> [0,2048)
        int i = z * 32 + lane;
        ((float4*)(g_scr + SC_VEC))[i] = ((const float4*)x)[i];
    } else if (warp < KA_WARPS) {
        int row = warp - 748;                     // w_hh rows 0..1023
        const float4* W = (const float4*)w_hh + (size_t)row * 512;
        float s = row_dot(W, h4, lane);
        s = warp_sum(s);
        if (lane == 0) g_scr[SC_GH + row] = s;
    }
}

// ============================================================
// kBC: blocks [0,112)   redundant softmax (L2-hot) + ctx partial (atomic)
//      blocks [112,368) w_hh rows 1024..3071 (warp per row, direct)
// ============================================================
#define KBC_BLOCKS 368
__global__ __launch_bounds__(256) void kBC(
    const float* __restrict__ h, const float* __restrict__ attn_b,
    const float* __restrict__ enc, const float* __restrict__ w_hh,
    float* __restrict__ out)
{
    int tid = threadIdx.x;

    if (blockIdx.x < 112) {
        __shared__ float sw[L];
        __shared__ float red[256];
        float m = -INFINITY;
        for (int i = tid; i < L; i += 256) {
            float v = g_lp[0][i] + g_lp[1][i] + attn_b[i];
            sw[i] = v; m = fmaxf(m, v);
        }
        red[tid] = m; __syncthreads();
        #pragma unroll
        for (int s = 128; s > 0; s >>= 1) { if (tid < s) red[tid] = fmaxf(red[tid], red[tid+s]); __syncthreads(); }
        float mx = red[0]; __syncthreads();

        float sum = 0.f;
        for (int i = tid; i < L; i += 256) { float e = __expf(sw[i] - mx); sw[i] = e; sum += e; }
        red[tid] = sum; __syncthreads();
        #pragma unroll
        for (int s = 128; s > 0; s >>= 1) { if (tid < s) red[tid] += red[tid+s]; __syncthreads(); }
        float inv = 1.f / red[0]; __syncthreads();
        for (int i = tid; i < L; i += 256) sw[i] *= inv;
        __syncthreads();

        if (blockIdx.x == 0)
            for (int i = tid; i < L; i += 256) out[2*H + i] = sw[i];

        int bx = blockIdx.x & 7, by = blockIdx.x >> 3;
        int j  = bx * 256 + tid;
        int r0 = by * 25;
        const float* e = enc + (size_t)r0 * H + j;
        float acc = 0.f;
        #pragma unroll
        for (int i = 0; i < 25; ++i)
            acc += sw[r0 + i] * e[(size_t)i * H];
        atomicAdd(&g_scr[SC_CTX + j], acc);
    } else {
        int lane = tid & 31;
        int row = 1024 + (blockIdx.x - 112) * 8 + (tid >> 5);  // 1024..3071
        const float4* W = (const float4*)w_hh + (size_t)row * 512;
        float s = row_dot(W, (const float4*)h, lane);
        s = warp_sum(s);
        if (lane == 0) g_scr[SC_GH + row] = s;
    }
}

// ============================================================
// kD: blocks [0,1024)     comb_W @ [x;ctx], warp per (row,quarter), atomic
//     blocks [1024,1408)  w_hh rows 3072..6143 (warp per row, direct)
// No block tails.
// ============================================================
#define KD_BLOCKS 1408
__global__ __launch_bounds__(256) void kD(
    const float* __restrict__ h,
    const float* __restrict__ comb_W, const float* __restrict__ w_hh)
{
    int tid  = threadIdx.x;
    int lane = tid & 31;

    if (blockIdx.x < 1024) {
        int gw = blockIdx.x * 8 + (tid >> 5);
        int row = gw >> 2, q = gw & 3;                 // 2048 rows x 4 quarters
        const float4* W = (const float4*)comb_W + (size_t)row * 1024 + q * 256;
        const float4* v = (const float4*)(g_scr + SC_VEC) + q * 256;
        float s = seg_dot8(W, v, lane);
        s = warp_sum(s);
        if (lane == 0) atomicAdd(&g_scr[SC_GSUM + row], s);
    } else {
        int row = 3072 + (blockIdx.x - 1024) * 8 + (tid >> 5);  // 3072..6143
        const float4* W = (const float4*)w_hh + (size_t)row * 512;
        float s = row_dot(W, (const float4*)h, lane);
        s = warp_sum(s);
        if (lane == 0) g_scr[SC_GH + row] = s;
    }
}

// ============================================================
// kE: fused final stage, occupancy-fixed. 512 blocks x 8 warps.
//   stage: g = relu(gsum + comb_b) -> smem
//   warp (col j, half hf): 3 half-row dots (w_ih rows j, j+H, j+2H),
//   pairs combine via smem; 4 threads do GRU gate math + write out.
// ============================================================
#define KE_BLOCKS 512
__global__ __launch_bounds__(256) void kE(
    const float* __restrict__ w_ih, const float* __restrict__ comb_b,
    const float* __restrict__ h, const float* __restrict__ b_ih,
    const float* __restrict__ b_hh, float* __restrict__ out)
{
    __shared__ __align__(16) float sg[H];
    __shared__ float pr[8][3];
    int tid  = threadIdx.x;
    int lane = tid & 31;
    int wid  = tid >> 5;

    // stage g = relu(gsum + comb_b)
    const float4* gs = (const float4*)(g_scr + SC_GSUM);
    const float4* cb = (const float4*)comb_b;
    float4* sg4 = (float4*)sg;
    #pragma unroll
    for (int i = tid; i < 512; i += 256) {
        float4 gv = gs[i], bv = cb[i];
        sg4[i] = make_float4(fmaxf(gv.x + bv.x, 0.f), fmaxf(gv.y + bv.y, 0.f),
                             fmaxf(gv.z + bv.z, 0.f), fmaxf(gv.w + bv.w, 0.f));
    }
    __syncthreads();

    int j  = blockIdx.x * 4 + (wid >> 1);         // output column 0..2047
    int hf = wid & 1;
    const float4* v  = (const float4*)sg + hf * 256;
    const float4* Wr = (const float4*)w_ih + (size_t)j * 512         + hf * 256;
    const float4* Wz = (const float4*)w_ih + (size_t)(j + H) * 512   + hf * 256;
    const float4* Wn = (const float4*)w_ih + (size_t)(j + 2*H) * 512 + hf * 256;

    float sr = seg_dot8(Wr, v, lane);
    float sz = seg_dot8(Wz, v, lane);
    float sn = seg_dot8(Wn, v, lane);
    sr = warp_sum(sr); sz = warp_sum(sz); sn = warp_sum(sn);
    if (lane == 0) { pr[wid][0] = sr; pr[wid][1] = sz; pr[wid][2] = sn; }
    __syncthreads();

    if (tid < 4) {
        int jj = blockIdx.x * 4 + tid;
        float fr = pr[tid*2][0] + pr[tid*2+1][0];
        float fz = pr[tid*2][1] + pr[tid*2+1][1];
        float fn = pr[tid*2][2] + pr[tid*2+1][2];
        float hr = g_scr[SC_GH + jj]       + b_hh[jj];
        float hz = g_scr[SC_GH + jj + H]   + b_hh[jj + H];
        float hn = g_scr[SC_GH + jj + 2*H] + b_hh[jj + 2*H];
        float ir = fr + b_ih[jj]       + hr;
        float iz = fz + b_ih[jj + H]   + hz;
        float r  = 1.f / (1.f + __expf(-ir));
        float z  = 1.f / (1.f + __expf(-iz));
        float n  = tanhf(fn + b_ih[jj + 2*H] + r * hn);
        float hv = (1.f - z) * n + z * h[jj];
        out[jj]     = hv;
        out[H + jj] = hv;
    }
}

// ============================================================
extern "C" void kernel_launch(void* const* d_in, const int* in_sizes, int n_in,
                              void* d_out, int out_size)
{
    const float* x      = (const float*)d_in[0];
    const float* h      = (const float*)d_in[1];
    const float* enc    = (const float*)d_in[2];
    const float* attn_W = (const float*)d_in[3];
    const float* attn_b = (const float*)d_in[4];
    const float* comb_W = (const float*)d_in[5];
    const float* comb_b = (const float*)d_in[6];
    const float* w_ih   = (const float*)d_in[7];
    const float* w_hh   = (const float*)d_in[8];
    const float* b_ih   = (const float*)d_in[9];
    const float* b_hh   = (const float*)d_in[10];
    float* out = (float*)d_out;

    kA<<<KA_BLOCKS, 256>>>(x, h, attn_W, w_hh);
    kBC<<<KBC_BLOCKS, 256>>>(h, attn_b, enc, w_hh, out);
    kD<<<KD_BLOCKS, 256>>>(h, comb_W, w_hh);
    kE<<<KE_BLOCKS, 256>>>(w_ih, comb_b, h, b_ih, b_hh, out);
}

// round 17
// speedup vs baseline: 1.2755x; 1.0008x over previous
#include <cuda_runtime.h>
#include <cstdint>
#include <math.h>

#define H 2048
#define L 350

// -------- persistent scratch (no allocs allowed) --------
__device__ float g_lp[2][L];               // attn logit partials (x-half, h-half)
// layout: [0,2048) x copy | [2048,4096) ctx (atomic, zeroed) |
// [4096,6144) gsum (atomic, zeroed) | [12288,18432) gh (direct)
#define SC_VEC   0
#define SC_CTX   2048
#define SC_GSUM  4096
#define SC_GH    12288
#define SC_TOTAL 18432
__device__ __align__(16) float g_scr[SC_TOTAL];

__device__ __forceinline__ float warp_sum(float v) {
    #pragma unroll
    for (int o = 16; o > 0; o >>= 1) v += __shfl_xor_sync(0xffffffffu, v, o);
    return v;
}
__device__ __forceinline__ float dot4(float4 a, float4 b) {
    return a.x*b.x + a.y*b.y + a.z*b.z + a.w*b.w;
}

// Proven unit: ONE front-batched burst of 8 LDG.128 (32 regs resident),
// then 8 dots against a hot vector (global-L2 or smem). 256 float4 segment.
__device__ __forceinline__ float seg_dot8(
    const float4* __restrict__ W, const float4* V, int lane)
{
    float4 w[8];
    #pragma unroll
    for (int u = 0; u < 8; u++) w[u] = __ldcs(&W[lane + 32*u]);
    float s = 0.f;
    #pragma unroll
    for (int u = 0; u < 8; u++) s += dot4(w[u], V[lane + 32*u]);
    return s;
}

// Full 2048-col row (512 f4): two sequential bursts.
__device__ __forceinline__ float row_dot(
    const float4* __restrict__ W, const float4* V, int lane)
{
    return seg_dot8(W, V, lane) + seg_dot8(W + 256, V + 256, lane);
}

// ============================================================
// kA: warps [0,700)     attn logit partials (warp per (row,half))
//     warps [700,732)   zero ctx+gsum [2048,6144)
//     warps [732,748)   copy x -> g_scr[SC_VEC]
//     warps [748,1772)  w_hh rows 0..1023 (warp per row, direct store)
// ============================================================
#define KA_WARPS 1772
#define KA_BLOCKS ((KA_WARPS + 7) / 8)
__global__ __launch_bounds__(256) void kA(
    const float* __restrict__ x, const float* __restrict__ h,
    const float* __restrict__ attn_W, const float* __restrict__ w_hh)
{
    int warp = (blockIdx.x * blockDim.x + threadIdx.x) >> 5;
    int lane = threadIdx.x & 31;
    const float4* h4 = (const float4*)h;

    if (warp < 700) {
        int row = warp >> 1, half = warp & 1;
        const float4* W = (const float4*)(attn_W + (size_t)row * 2 * H) + half * 512;
        const float4* v = (const float4*)(half ? h : x);
        float s = row_dot(W, v, lane);
        s = warp_sum(s);
        if (lane == 0) g_lp[half][row] = s;
    } else if (warp < 732) {
        int z = warp - 700;                       // zero [2048,6144): 32 warps
        *(float4*)(g_scr + 2048 + z * 128 + lane * 4) = make_float4(0.f,0.f,0.f,0.f);
    } else if (warp < 748) {
        int z = warp - 732;                       // copy x -> [0,2048)
        int i = z * 32 + lane;
        ((float4*)(g_scr + SC_VEC))[i] = ((const float4*)x)[i];
    } else if (warp < KA_WARPS) {
        int row = warp - 748;                     // w_hh rows 0..1023
        const float4* W = (const float4*)w_hh + (size_t)row * 512;
        float s = row_dot(W, h4, lane);
        s = warp_sum(s);
        if (lane == 0) g_scr[SC_GH + row] = s;
    }
}

// ============================================================
// kBC: blocks [0,112)   redundant softmax (L2-hot) + ctx partial (atomic)
//      blocks [112,368) w_hh rows 1024..3071 (warp per row, direct)
// ============================================================
#define KBC_BLOCKS 368
__global__ __launch_bounds__(256) void kBC(
    const float* __restrict__ h, const float* __restrict__ attn_b,
    const float* __restrict__ enc, const float* __restrict__ w_hh,
    float* __restrict__ out)
{
    int tid = threadIdx.x;

    if (blockIdx.x < 112) {
        __shared__ float sw[L];
        __shared__ float red[256];
        float m = -INFINITY;
        for (int i = tid; i < L; i += 256) {
            float v = g_lp[0][i] + g_lp[1][i] + attn_b[i];
            sw[i] = v; m = fmaxf(m, v);
        }
        red[tid] = m; __syncthreads();
        #pragma unroll
        for (int s = 128; s > 0; s >>= 1) { if (tid < s) red[tid] = fmaxf(red[tid], red[tid+s]); __syncthreads(); }
        float mx = red[0]; __syncthreads();

        float sum = 0.f;
        for (int i = tid; i < L; i += 256) { float e = __expf(sw[i] - mx); sw[i] = e; sum += e; }
        red[tid] = sum; __syncthreads();
        #pragma unroll
        for (int s = 128; s > 0; s >>= 1) { if (tid < s) red[tid] += red[tid+s]; __syncthreads(); }
        float inv = 1.f / red[0]; __syncthreads();
        for (int i = tid; i < L; i += 256) sw[i] *= inv;
        __syncthreads();

        if (blockIdx.x == 0)
            for (int i = tid; i < L; i += 256) out[2*H + i] = sw[i];

        int bx = blockIdx.x & 7, by = blockIdx.x >> 3;
        int j  = bx * 256 + tid;
        int r0 = by * 25;
        const float* e = enc + (size_t)r0 * H + j;
        float acc = 0.f;
        #pragma unroll
        for (int i = 0; i < 25; ++i)
            acc += sw[r0 + i] * e[(size_t)i * H];
        atomicAdd(&g_scr[SC_CTX + j], acc);
    } else {
        int lane = tid & 31;
        int row = 1024 + (blockIdx.x - 112) * 8 + (tid >> 5);  // 1024..3071
        const float4* W = (const float4*)w_hh + (size_t)row * 512;
        float s = row_dot(W, (const float4*)h, lane);
        s = warp_sum(s);
        if (lane == 0) g_scr[SC_GH + row] = s;
    }
}

// ============================================================
// kD: blocks [0,1024)     comb_W @ [x;ctx], warp per (row,quarter), atomic
//     blocks [1024,1408)  w_hh rows 3072..6143 (warp per row, direct)
// No block tails.
// ============================================================
#define KD_BLOCKS 1408
__global__ __launch_bounds__(256) void kD(
    const float* __restrict__ h,
    const float* __restrict__ comb_W, const float* __restrict__ w_hh)
{
    int tid  = threadIdx.x;
    int lane = tid & 31;

    if (blockIdx.x < 1024) {
        int gw = blockIdx.x * 8 + (tid >> 5);
        int row = gw >> 2, q = gw & 3;                 // 2048 rows x 4 quarters
        const float4* W = (const float4*)comb_W + (size_t)row * 1024 + q * 256;
        const float4* v = (const float4*)(g_scr + SC_VEC) + q * 256;
        float s = seg_dot8(W, v, lane);
        s = warp_sum(s);
        if (lane == 0) atomicAdd(&g_scr[SC_GSUM + row], s);
    } else {
        int row = 3072 + (blockIdx.x - 1024) * 8 + (tid >> 5);  // 3072..6143
        const float4* W = (const float4*)w_hh + (size_t)row * 512;
        float s = row_dot(W, (const float4*)h, lane);
        s = warp_sum(s);
        if (lane == 0) g_scr[SC_GH + row] = s;
    }
}

// ============================================================
// kE: fused final stage, high-occupancy. 1024 blocks x 8 warps (8192 warps).
//   stage: g = relu(gsum + comb_b) -> smem
//   warp (col j, quarter q): 12 interleaved front-batched LDG.128
//   (burst-4 from each gate row j, j+H, j+2H), then 12 smem dots.
//   4 warps per column combine via smem; 2 threads do gate math + write out.
// ============================================================
#define KE_BLOCKS 1024
__global__ __launch_bounds__(256) void kE(
    const float* __restrict__ w_ih, const float* __restrict__ comb_b,
    const float* __restrict__ h, const float* __restrict__ b_ih,
    const float* __restrict__ b_hh, float* __restrict__ out)
{
    __shared__ __align__(16) float sg[H];
    __shared__ float pr[8][3];
    int tid  = threadIdx.x;
    int lane = tid & 31;
    int wid  = tid >> 5;

    // stage g = relu(gsum + comb_b)
    const float4* gs = (const float4*)(g_scr + SC_GSUM);
    const float4* cb = (const float4*)comb_b;
    float4* sg4 = (float4*)sg;
    #pragma unroll
    for (int i = tid; i < 512; i += 256) {
        float4 gv = gs[i], bv = cb[i];
        sg4[i] = make_float4(fmaxf(gv.x + bv.x, 0.f), fmaxf(gv.y + bv.y, 0.f),
                             fmaxf(gv.z + bv.z, 0.f), fmaxf(gv.w + bv.w, 0.f));
    }
    __syncthreads();

    int j = blockIdx.x * 2 + (wid >> 2);          // output column 0..2047
    int q = wid & 3;                              // quarter 0..3
    const float4* v  = (const float4*)sg + q * 128;
    const float4* Wr = (const float4*)w_ih + (size_t)j * 512         + q * 128;
    const float4* Wz = (const float4*)w_ih + (size_t)(j + H) * 512   + q * 128;
    const float4* Wn = (const float4*)w_ih + (size_t)(j + 2*H) * 512 + q * 128;

    // 12 front-batched loads (3 gate streams x burst-4), then 12 dots
    float4 wr[4], wz[4], wn[4];
    #pragma unroll
    for (int u = 0; u < 4; u++) wr[u] = __ldcs(&Wr[lane + 32*u]);
    #pragma unroll
    for (int u = 0; u < 4; u++) wz[u] = __ldcs(&Wz[lane + 32*u]);
    #pragma unroll
    for (int u = 0; u < 4; u++) wn[u] = __ldcs(&Wn[lane + 32*u]);

    float sr = 0.f, sz = 0.f, sn = 0.f;
    #pragma unroll
    for (int u = 0; u < 4; u++) {
        float4 vv = v[lane + 32*u];
        sr += dot4(wr[u], vv);
        sz += dot4(wz[u], vv);
        sn += dot4(wn[u], vv);
    }
    sr = warp_sum(sr); sz = warp_sum(sz); sn = warp_sum(sn);
    if (lane == 0) { pr[wid][0] = sr; pr[wid][1] = sz; pr[wid][2] = sn; }
    __syncthreads();

    if (tid < 2) {
        int jj = blockIdx.x * 2 + tid;
        int b0 = tid * 4;
        float fr = pr[b0][0] + pr[b0+1][0] + pr[b0+2][0] + pr[b0+3][0];
        float fz = pr[b0][1] + pr[b0+1][1] + pr[b0+2][1] + pr[b0+3][1];
        float fn = pr[b0][2] + pr[b0+1][2] + pr[b0+2][2] + pr[b0+3][2];
        float hr = g_scr[SC_GH + jj]       + b_hh[jj];
        float hz = g_scr[SC_GH + jj + H]   + b_hh[jj + H];
        float hn = g_scr[SC_GH + jj + 2*H] + b_hh[jj + 2*H];
        float ir = fr + b_ih[jj]       + hr;
        float iz = fz + b_ih[jj + H]   + hz;
        float r  = 1.f / (1.f + __expf(-ir));
        float z  = 1.f / (1.f + __expf(-iz));
        float n  = tanhf(fn + b_ih[jj + 2*H] + r * hn);
        float hv = (1.f - z) * n + z * h[jj];
        out[jj]     = hv;
        out[H + jj] = hv;
    }
}

// ============================================================
extern "C" void kernel_launch(void* const* d_in, const int* in_sizes, int n_in,
                              void* d_out, int out_size)
{
    const float* x      = (const float*)d_in[0];
    const float* h      = (const float*)d_in[1];
    const float* enc    = (const float*)d_in[2];
    const float* attn_W = (const float*)d_in[3];
    const float* attn_b = (const float*)d_in[4];
    const float* comb_W = (const float*)d_in[5];
    const float* comb_b = (const float*)d_in[6];
    const float* w_ih   = (const float*)d_in[7];
    const float* w_hh   = (const float*)d_in[8];
    const float* b_ih   = (const float*)d_in[9];
    const float* b_hh   = (const float*)d_in[10];
    float* out = (float*)d_out;

    kA<<<KA_BLOCKS, 256>>>(x, h, attn_W, w_hh);
    kBC<<<KBC_BLOCKS, 256>>>(h, attn_b, enc, w_hh, out);
    kD<<<KD_BLOCKS, 256>>>(h, comb_W, w_hh);
    kE<<<KE_BLOCKS, 256>>>(w_ih, comb_b, h, b_ih, b_hh, out);
}